// round 11
// baseline (speedup 1.0000x reference)
#include <cuda_runtime.h>
#include <math.h>

#define NN 49152
#define NE 393216
#define DIM 256
#define EEMB 128
#define DEPTH 4

// ---- scratch (static device globals; no runtime allocation) ----
__device__ float g_e[(size_t)NE * EEMB];     // edge embeddings (tf32-rounded)
__device__ float g_hid[(size_t)NE * EEMB];   // edge-embed hidden (tf32-rounded)
__device__ float g_P[(size_t)NN * DIM];      // h @ Wa + b
__device__ float g_Q[(size_t)NN * DIM];      // h @ Wb
__device__ float g_hA[(size_t)NN * DIM];
__device__ float g_hB[(size_t)NN * DIM];
__device__ float g_x[(size_t)NN * DIM];
__device__ float g_wt[1851392];              // tf32-pre-rounded weights

// weight offsets inside g_wt (floats)
#define WOFF_FF1  0
#define WOFF_MP1  262144
#define WOFF_MP2  917504
#define WOFF_FF2  1572864
#define WOFF_EEW2 1835008

#define B_E   0
#define B_P   2
#define B_Q   3
#define B_HA  4
#define B_HB  5
#define B_X   6
#define B_HID 7

__device__ __forceinline__ float* bufsel(int id) {
    switch (id) {
        case B_E:   return g_e;
        case B_P:   return g_P;
        case B_Q:   return g_Q;
        case B_HA:  return g_hA;
        case B_HB:  return g_hB;
        case B_HID: return g_hid;
        default:    return g_x;
    }
}

__device__ __forceinline__ float gelu_f(float v) {
    return 0.5f * v * (1.0f + erff(v * 0.70710678118654752440f));
}

__device__ __forceinline__ unsigned tf32r(float f) {
    unsigned u;
    asm("cvt.rna.tf32.f32 %0, %1;" : "=r"(u) : "f"(f));
    return u;
}

__device__ __forceinline__ void mma_tf32(float* c, const unsigned* a, const unsigned* b) {
    asm volatile(
        "mma.sync.aligned.m16n8k8.row.col.f32.tf32.tf32.f32 "
        "{%0,%1,%2,%3}, {%4,%5,%6,%7}, {%8,%9}, {%0,%1,%2,%3};\n"
        : "+f"(c[0]), "+f"(c[1]), "+f"(c[2]), "+f"(c[3])
        : "r"(a[0]), "r"(a[1]), "r"(a[2]), "r"(a[3]), "r"(b[0]), "r"(b[1]));
}

__device__ __forceinline__ void cp16(unsigned dst, const void* src) {
    asm volatile("cp.async.cg.shared.global [%0], [%1], 16;"
                 :: "r"(dst), "l"(src));
}

// ---------------------------------------------------------------------------
// weight pre-rounding
// ---------------------------------------------------------------------------
__global__ void cvtw_k(const float* __restrict__ src, int dstOff4, int n4) {
    int i = blockIdx.x * blockDim.x + threadIdx.x;
    if (i < n4) {
        float4 v = ((const float4*)src)[i];
        float4 o;
        o.x = __uint_as_float(tf32r(v.x));
        o.y = __uint_as_float(tf32r(v.y));
        o.z = __uint_as_float(tf32r(v.z));
        o.w = __uint_as_float(tf32r(v.w));
        ((float4*)g_wt)[dstOff4 + i] = o;
    }
}

// ---------------------------------------------------------------------------
// input copy
// ---------------------------------------------------------------------------
__global__ void copy_in_k(const float* __restrict__ s, int did, int n4) {
    int i = blockIdx.x * blockDim.x + threadIdx.x;
    if (i < n4) ((float4*)bufsel(did))[i] = ((const float4*)s)[i];
}

// ---------------------------------------------------------------------------
// edge embedder layer 1: g_hid = round_tf32(gelu(attr @ w1 + b1))
// ---------------------------------------------------------------------------
__global__ void __launch_bounds__(256) ee1_k(
    const float* __restrict__ attr,
    const float* __restrict__ w1, const float* __restrict__ b1)
{
    const int sub = threadIdx.x >> 7;
    const int j   = threadIdx.x & 127;
    const int e   = blockIdx.x * 2 + sub;

    float4 a = *(const float4*)(attr + (size_t)e * 4);
    float t = b1[j] + a.x * __ldg(w1 + j) + a.y * __ldg(w1 + EEMB + j)
                    + a.z * __ldg(w1 + 2 * EEMB + j) + a.w * __ldg(w1 + 3 * EEMB + j);
    g_hid[(size_t)e * EEMB + j] = __uint_as_float(tf32r(gelu_f(t)));
}

// ---------------------------------------------------------------------------
// tf32 tensor-core GEMM (cp.async double-buffered, single-sync pipeline).
//   C[M x N] = act(A[M x K] @ W[K x N] + bias)[+res]
//   ACVT=1: A fragments cvt.rna'd at read (dirty/unrounded A buffers).
//   ACVT=0: A buffer is pre-rounded tf32 bits -> raw reinterpret.
//   RND=1 : round output stores to tf32 (for buffers later used as clean A).
// ---------------------------------------------------------------------------
template<int ACT, int ACVT, int RND>
__global__ void __launch_bounds__(256, 2) mma_gemm_k(
    int Aid, int wOff, const float* __restrict__ bias,
    int resId, int dupId, int Cid, float* __restrict__ Cext,
    int K, int ldW, int ldC)
{
    __shared__ float As[2][128][20];
    __shared__ float Bs[2][16][136];

    const float* __restrict__ A = bufsel(Aid);
    const float* __restrict__ W = g_wt + wOff;
    float* __restrict__ C = Cext ? Cext : bufsel(Cid);

    const int tid  = threadIdx.x;
    const int bm   = blockIdx.x * 128;
    const int bn   = blockIdx.y * 128;
    const int w    = tid >> 5;
    const int lane = tid & 31;
    const int g    = lane >> 2;
    const int tq   = lane & 3;
    const int wm   = (w & 1) * 64;
    const int wn   = (w >> 1) * 32;

    const int ar  = tid & 127;
    const int ak0 = tid >> 7;
    const int bk0 = tid >> 5;
    const int bq  = (tid & 31) * 4;

    const float* Ag  = A + (size_t)(bm + ar) * K;
    const float* Wg0 = W + (size_t)bk0 * ldW + bn + bq;
    const float* Wg1 = W + (size_t)(bk0 + 8) * ldW + bn + bq;

    unsigned dA0[2], dA1[2], dB0[2], dB1[2];
#pragma unroll
    for (int s = 0; s < 2; s++) {
        dA0[s] = (unsigned)__cvta_generic_to_shared(&As[s][ar][ak0 * 4]);
        dA1[s] = (unsigned)__cvta_generic_to_shared(&As[s][ar][(ak0 + 2) * 4]);
        dB0[s] = (unsigned)__cvta_generic_to_shared(&Bs[s][bk0][bq]);
        dB1[s] = (unsigned)__cvta_generic_to_shared(&Bs[s][bk0 + 8][bq]);
    }

    float acc[4][4][4];
#pragma unroll
    for (int mi = 0; mi < 4; mi++)
#pragma unroll
        for (int ni = 0; ni < 4; ni++)
#pragma unroll
            for (int r = 0; r < 4; r++) acc[mi][ni][r] = 0.f;

    cp16(dA0[0], Ag + ak0 * 4);
    cp16(dA1[0], Ag + (ak0 + 2) * 4);
    cp16(dB0[0], Wg0);
    cp16(dB1[0], Wg1);
    asm volatile("cp.async.commit_group;" ::: "memory");

    const int niter = K / 16;
    for (int it = 0; it < niter; it++) {
        const int cur = it & 1;
        // single-sync pipeline: wait cur, barrier proves nxt buffer free,
        // THEN refill nxt, then compute cur.
        asm volatile("cp.async.wait_group 0;" ::: "memory");
        __syncthreads();
        if (it + 1 < niter) {
            const int nxt = (it + 1) & 1;
            const int k0  = (it + 1) * 16;
            cp16(dA0[nxt], Ag + k0 + ak0 * 4);
            cp16(dA1[nxt], Ag + k0 + (ak0 + 2) * 4);
            cp16(dB0[nxt], Wg0 + (size_t)k0 * ldW);
            cp16(dB1[nxt], Wg1 + (size_t)k0 * ldW);
            asm volatile("cp.async.commit_group;" ::: "memory");
        }

#pragma unroll
        for (int kb2 = 0; kb2 < 2; kb2++) {
            const int kb = kb2 * 8;
            unsigned a[4][4], b[4][2];
#pragma unroll
            for (int mi = 0; mi < 4; mi++) {
                const int m0 = wm + mi * 16 + g;
                if (ACVT) {
                    a[mi][0] = tf32r(As[cur][m0][kb + tq]);
                    a[mi][1] = tf32r(As[cur][m0 + 8][kb + tq]);
                    a[mi][2] = tf32r(As[cur][m0][kb + tq + 4]);
                    a[mi][3] = tf32r(As[cur][m0 + 8][kb + tq + 4]);
                } else {
                    a[mi][0] = __float_as_uint(As[cur][m0][kb + tq]);
                    a[mi][1] = __float_as_uint(As[cur][m0 + 8][kb + tq]);
                    a[mi][2] = __float_as_uint(As[cur][m0][kb + tq + 4]);
                    a[mi][3] = __float_as_uint(As[cur][m0 + 8][kb + tq + 4]);
                }
            }
#pragma unroll
            for (int ni = 0; ni < 4; ni++) {
                const int n0 = wn + ni * 8 + g;
                b[ni][0] = __float_as_uint(Bs[cur][kb + tq][n0]);
                b[ni][1] = __float_as_uint(Bs[cur][kb + tq + 4][n0]);
            }
#pragma unroll
            for (int mi = 0; mi < 4; mi++)
#pragma unroll
                for (int ni = 0; ni < 4; ni++)
                    mma_tf32(acc[mi][ni], a[mi], b[ni]);
        }
    }

    const float* res = (resId >= 0) ? bufsel(resId) : nullptr;
    float* dup = (dupId >= 0) ? bufsel(dupId) : nullptr;
#pragma unroll
    for (int mi = 0; mi < 4; mi++) {
#pragma unroll
        for (int h = 0; h < 2; h++) {
            const int row = bm + wm + mi * 16 + g + h * 8;
#pragma unroll
            for (int ni = 0; ni < 4; ni++) {
                const int c = bn + wn + ni * 8 + tq * 2;
                float v0 = acc[mi][ni][h * 2 + 0];
                float v1 = acc[mi][ni][h * 2 + 1];
                if (bias) {
                    float2 bb = *(const float2*)(bias + c);
                    v0 += bb.x; v1 += bb.y;
                }
                if (ACT == 1) { v0 = gelu_f(v0); v1 = gelu_f(v1); }
                const size_t off = (size_t)row * ldC + c;
                if (res) {
                    float2 r = *(const float2*)(res + off);
                    v0 += r.x; v1 += r.y;
                }
                if (RND) {
                    v0 = __uint_as_float(tf32r(v0));
                    v1 = __uint_as_float(tf32r(v1));
                }
                if (dup) {
                    const size_t offA = (size_t)row * K + c;
                    *(float2*)(dup + offA) = *(const float2*)(A + offA);
                }
                float2 o; o.x = v0; o.y = v1;
                *(float2*)(C + off) = o;
            }
        }
    }
}

// ---------------------------------------------------------------------------
// FUSED edge GEMM + scatter. A = g_e is pre-rounded tf32 -> no A cvt.
// Single-sync pipeline.
// ---------------------------------------------------------------------------
__global__ void __launch_bounds__(256, 2) mma_edge_k(
    int wOff, const int* __restrict__ ei, int Cid)
{
    __shared__ float As[2][128][20];
    __shared__ float Bs[2][16][136];
    __shared__ int sSrc[128], sDst[128];

    const float* __restrict__ A = g_e;
    const float* __restrict__ W = g_wt + wOff;
    float* __restrict__ C = bufsel(Cid);

    const int tid  = threadIdx.x;
    const int bm   = blockIdx.x * 128;
    const int bn   = blockIdx.y * 128;
    const int w    = tid >> 5;
    const int lane = tid & 31;
    const int g    = lane >> 2;
    const int tq   = lane & 3;
    const int wm   = (w & 1) * 64;
    const int wn   = (w >> 1) * 32;

    if (tid < 128) {
        sSrc[tid] = ei[bm + tid];
        sDst[tid] = ei[NE + bm + tid];
    }

    const int ar  = tid & 127;
    const int ak0 = tid >> 7;
    const int bk0 = tid >> 5;
    const int bq  = (tid & 31) * 4;

    const float* Ag  = A + (size_t)(bm + ar) * EEMB;
    const float* Wg0 = W + (size_t)bk0 * DIM + bn + bq;
    const float* Wg1 = W + (size_t)(bk0 + 8) * DIM + bn + bq;

    unsigned dA0[2], dA1[2], dB0[2], dB1[2];
#pragma unroll
    for (int s = 0; s < 2; s++) {
        dA0[s] = (unsigned)__cvta_generic_to_shared(&As[s][ar][ak0 * 4]);
        dA1[s] = (unsigned)__cvta_generic_to_shared(&As[s][ar][(ak0 + 2) * 4]);
        dB0[s] = (unsigned)__cvta_generic_to_shared(&Bs[s][bk0][bq]);
        dB1[s] = (unsigned)__cvta_generic_to_shared(&Bs[s][bk0 + 8][bq]);
    }

    float acc[4][4][4];
#pragma unroll
    for (int mi = 0; mi < 4; mi++)
#pragma unroll
        for (int ni = 0; ni < 4; ni++)
#pragma unroll
            for (int r = 0; r < 4; r++) acc[mi][ni][r] = 0.f;

    cp16(dA0[0], Ag + ak0 * 4);
    cp16(dA1[0], Ag + (ak0 + 2) * 4);
    cp16(dB0[0], Wg0);
    cp16(dB1[0], Wg1);
    asm volatile("cp.async.commit_group;" ::: "memory");

    const int niter = EEMB / 16;   // 8
    for (int it = 0; it < niter; it++) {
        const int cur = it & 1;
        asm volatile("cp.async.wait_group 0;" ::: "memory");
        __syncthreads();
        if (it + 1 < niter) {
            const int nxt = (it + 1) & 1;
            const int k0  = (it + 1) * 16;
            cp16(dA0[nxt], Ag + k0 + ak0 * 4);
            cp16(dA1[nxt], Ag + k0 + (ak0 + 2) * 4);
            cp16(dB0[nxt], Wg0 + (size_t)k0 * DIM);
            cp16(dB1[nxt], Wg1 + (size_t)k0 * DIM);
            asm volatile("cp.async.commit_group;" ::: "memory");
        }

#pragma unroll
        for (int kb2 = 0; kb2 < 2; kb2++) {
            const int kb = kb2 * 8;
            unsigned a[4][4], b[4][2];
#pragma unroll
            for (int mi = 0; mi < 4; mi++) {
                const int m0 = wm + mi * 16 + g;
                a[mi][0] = __float_as_uint(As[cur][m0][kb + tq]);
                a[mi][1] = __float_as_uint(As[cur][m0 + 8][kb + tq]);
                a[mi][2] = __float_as_uint(As[cur][m0][kb + tq + 4]);
                a[mi][3] = __float_as_uint(As[cur][m0 + 8][kb + tq + 4]);
            }
#pragma unroll
            for (int ni = 0; ni < 4; ni++) {
                const int n0 = wn + ni * 8 + g;
                b[ni][0] = __float_as_uint(Bs[cur][kb + tq][n0]);
                b[ni][1] = __float_as_uint(Bs[cur][kb + tq + 4][n0]);
            }
#pragma unroll
            for (int mi = 0; mi < 4; mi++)
#pragma unroll
                for (int ni = 0; ni < 4; ni++)
                    mma_tf32(acc[mi][ni], a[mi], b[ni]);
        }
    }
    __syncthreads();   // ensure sSrc/sDst visible + all MMA consumers done

    // fused scatter epilogue (v4 reductions via lane^1 butterfly)
    const bool odd = (tq & 1);
#pragma unroll
    for (int mi = 0; mi < 4; mi++) {
#pragma unroll
        for (int h = 0; h < 2; h++) {
            const int lr = wm + mi * 16 + g + h * 8;
            const int s = sSrc[lr];
            const int d = sDst[lr];
            const float* Pp = g_P + (size_t)s * DIM;
            const float* Qp = g_Q + (size_t)d * DIM;
            float* Op = C + (size_t)d * DIM;
#pragma unroll
            for (int p = 0; p < 2; p++) {
                float s0 = odd ? acc[mi][2*p][h*2+0] : acc[mi][2*p+1][h*2+0];
                float s1 = odd ? acc[mi][2*p][h*2+1] : acc[mi][2*p+1][h*2+1];
                float r0 = __shfl_xor_sync(0xffffffffu, s0, 1);
                float r1 = __shfl_xor_sync(0xffffffffu, s1, 1);
                float o0 = odd ? acc[mi][2*p+1][h*2+0] : acc[mi][2*p][h*2+0];
                float o1 = odd ? acc[mi][2*p+1][h*2+1] : acc[mi][2*p][h*2+1];
                float4 v;
                if (odd) { v.x = r0; v.y = r1; v.z = o0; v.w = o1; }
                else     { v.x = o0; v.y = o1; v.z = r0; v.w = r1; }

                const int c = bn + wn + p * 16 + (tq & 1) * 8 + (tq >> 1) * 4;
                float4 pv = *(const float4*)(Pp + c);
                float4 qv = *(const float4*)(Qp + c);
                v.x = gelu_f(v.x + pv.x + qv.x);
                v.y = gelu_f(v.y + pv.y + qv.y);
                v.z = gelu_f(v.z + pv.z + qv.z);
                v.w = gelu_f(v.w + pv.w + qv.w);

                asm volatile("red.global.add.v4.f32 [%0], {%1, %2, %3, %4};"
                             :: "l"(Op + c), "f"(v.x), "f"(v.y), "f"(v.z), "f"(v.w)
                             : "memory");
            }
        }
    }
}

// ---------------------------------------------------------------------------
extern "C" void kernel_launch(void* const* d_in, const int* in_sizes, int n_in,
                              void* d_out, int out_size)
{
    const float* x     = (const float*)d_in[0];
    const int*   ei    = (const int*)d_in[1];
    const float* attr  = (const float*)d_in[2];
    const float* ee_w1 = (const float*)d_in[3];
    const float* ee_b1 = (const float*)d_in[4];
    const float* ee_w2 = (const float*)d_in[5];
    const float* ee_b2 = (const float*)d_in[6];
    const float* ff1_w = (const float*)d_in[7];
    const float* ff1_b = (const float*)d_in[8];
    const float* mp1_w = (const float*)d_in[9];
    const float* mp1_b = (const float*)d_in[10];
    const float* mp2_w = (const float*)d_in[11];
    const float* mp2_b = (const float*)d_in[12];
    const float* ff2_w = (const float*)d_in[13];
    const float* ff2_b = (const float*)d_in[14];
    float* out = (float*)d_out;

    const int n4 = NN * DIM / 4;
    const int cb = (n4 + 255) / 256;
    const dim3 gN(NN / 128, 2);      // node GEMMs
    const dim3 gE(NE / 128, 2);      // fused edge GEMM+scatter
    const dim3 gEE(NE / 128, 1);     // edge-embed layer-2 GEMM (N=128)

    // pre-round all weights into g_wt (tf32 RNA)
    cvtw_k<<<(262144/4 + 255)/256, 256>>>(ff1_w, WOFF_FF1/4, 262144/4);
    cvtw_k<<<(655360/4 + 255)/256, 256>>>(mp1_w, WOFF_MP1/4, 655360/4);
    cvtw_k<<<(655360/4 + 255)/256, 256>>>(mp2_w, WOFF_MP2/4, 655360/4);
    cvtw_k<<<(262144/4 + 255)/256, 256>>>(ff2_w, WOFF_FF2/4, 262144/4);
    cvtw_k<<<(16384/4 + 255)/256, 256>>>(ee_w2, WOFF_EEW2/4, 16384/4);

    copy_in_k<<<cb, 256>>>(x, B_X, n4);

    // edge embedder: layer1 SIMT (rounded store), layer2 GEMM (ACVT=0, RND=1)
    ee1_k<<<NE / 2, 256>>>(attr, ee_w1, ee_b1);
    mma_gemm_k<0,0,1><<<gEE, 256>>>(B_HID, WOFF_EEW2, ee_b2, -1, -1, B_E, nullptr,
                                    EEMB, EEMB, EEMB);

    for (int i = 0; i < DEPTH; i++) {
        const int f1o = WOFF_FF1 + i * DIM * DIM;
        const int f2o = WOFF_FF2 + i * DIM * DIM;
        const int m1o = WOFF_MP1 + i * 640 * DIM;
        const int m2o = WOFF_MP2 + i * 640 * DIM;

        // hA = round(gelu(x @ ff1_w + b));  x dirty -> ACVT=1, RND=1
        mma_gemm_k<1,1,1><<<gN, 256>>>(B_X, f1o, ff1_b + i * DIM, -1, -1, B_HA, nullptr,
                                       DIM, DIM, DIM);

        // message pass 1: hA clean -> ACVT=0
        mma_gemm_k<0,0,0><<<gN, 256>>>(B_HA, m1o,             mp1_b + i * DIM, -1, -1,  B_P, nullptr, DIM, DIM, DIM);
        mma_gemm_k<0,0,0><<<gN, 256>>>(B_HA, m1o + 256 * DIM, nullptr,         -1, B_HB, B_Q, nullptr, DIM, DIM, DIM);
        mma_edge_k<<<gE, 256>>>(m1o + 512 * DIM, ei, B_HB);

        // message pass 2: hB dirty (fp32 aggregation) -> ACVT=1
        mma_gemm_k<0,1,0><<<gN, 256>>>(B_HB, m2o,             mp2_b + i * DIM, -1, -1,  B_P, nullptr, DIM, DIM, DIM);
        mma_gemm_k<0,1,0><<<gN, 256>>>(B_HB, m2o + 256 * DIM, nullptr,         -1, B_HA, B_Q, nullptr, DIM, DIM, DIM);
        mma_edge_k<<<gE, 256>>>(m2o + 512 * DIM, ei, B_HA);

        // x = x + hA @ ff2_w + b;  hA dirty -> ACVT=1; no store rounding
        mma_gemm_k<0,1,0><<<gN, 256>>>(B_HA, f2o, ff2_b + i * DIM, B_X, -1, B_X,
                                       (i == DEPTH - 1) ? out : nullptr, DIM, DIM, DIM);
    }
}

// round 15
// speedup vs baseline: 1.1111x; 1.1111x over previous
#include <cuda_runtime.h>
#include <math.h>

#define NN 49152
#define NE 393216
#define DIM 256
#define EEMB 128
#define DEPTH 4

// ---- scratch (static device globals; no runtime allocation) ----
__device__ float g_e[(size_t)NE * EEMB];     // edge embeddings
__device__ float g_hid[(size_t)NE * EEMB];   // edge-embed hidden layer
__device__ float g_P[(size_t)NN * DIM];      // h @ Wa + b
__device__ float g_Q[(size_t)NN * DIM];      // h @ Wb
__device__ float g_hA[(size_t)NN * DIM];
__device__ float g_hB[(size_t)NN * DIM];
__device__ float g_x[(size_t)NN * DIM];
__device__ float g_wt[1851392];              // tf32-pre-rounded weights

// weight offsets inside g_wt (floats) — [K,N] row-major, as delivered
#define WOFF_FF1  0
#define WOFF_MP1  262144
#define WOFF_MP2  917504
#define WOFF_FF2  1572864
#define WOFF_EEW2 1835008

#define B_E   0
#define B_P   2
#define B_Q   3
#define B_HA  4
#define B_HB  5
#define B_X   6
#define B_HID 7

__device__ __forceinline__ float* bufsel(int id) {
    switch (id) {
        case B_E:   return g_e;
        case B_P:   return g_P;
        case B_Q:   return g_Q;
        case B_HA:  return g_hA;
        case B_HB:  return g_hB;
        case B_HID: return g_hid;
        default:    return g_x;
    }
}

__device__ __forceinline__ float gelu_f(float v) {
    return 0.5f * v * (1.0f + erff(v * 0.70710678118654752440f));
}

__device__ __forceinline__ unsigned tf32r(float f) {
    unsigned u;
    asm("cvt.rna.tf32.f32 %0, %1;" : "=r"(u) : "f"(f));
    return u;
}

__device__ __forceinline__ void mma_tf32(float* c, const unsigned* a, const unsigned* b) {
    asm volatile(
        "mma.sync.aligned.m16n8k8.row.col.f32.tf32.tf32.f32 "
        "{%0,%1,%2,%3}, {%4,%5,%6,%7}, {%8,%9}, {%0,%1,%2,%3};\n"
        : "+f"(c[0]), "+f"(c[1]), "+f"(c[2]), "+f"(c[3])
        : "r"(a[0]), "r"(a[1]), "r"(a[2]), "r"(a[3]), "r"(b[0]), "r"(b[1]));
}

__device__ __forceinline__ void cp16(unsigned dst, const void* src) {
    asm volatile("cp.async.cg.shared.global [%0], [%1], 16;"
                 :: "r"(dst), "l"(src));
}

// ---------------------------------------------------------------------------
// weight pre-rounding (proven)
// ---------------------------------------------------------------------------
__global__ void cvtw_k(const float* __restrict__ src, int dstOff4, int n4) {
    int i = blockIdx.x * blockDim.x + threadIdx.x;
    if (i < n4) {
        float4 v = ((const float4*)src)[i];
        float4 o;
        o.x = __uint_as_float(tf32r(v.x));
        o.y = __uint_as_float(tf32r(v.y));
        o.z = __uint_as_float(tf32r(v.z));
        o.w = __uint_as_float(tf32r(v.w));
        ((float4*)g_wt)[dstOff4 + i] = o;
    }
}

__global__ void copy_in_k(const float* __restrict__ s, int did, int n4) {
    int i = blockIdx.x * blockDim.x + threadIdx.x;
    if (i < n4) ((float4*)bufsel(did))[i] = ((const float4*)s)[i];
}

// ---------------------------------------------------------------------------
// edge embedder layer 1 (proven): g_hid = round_tf32(gelu(attr @ w1 + b1))
// ---------------------------------------------------------------------------
__global__ void __launch_bounds__(256) ee1_k(
    const float* __restrict__ attr,
    const float* __restrict__ w1, const float* __restrict__ b1)
{
    const int sub = threadIdx.x >> 7;
    const int j   = threadIdx.x & 127;
    const int e   = blockIdx.x * 2 + sub;

    float4 a = *(const float4*)(attr + (size_t)e * 4);
    float t = b1[j] + a.x * __ldg(w1 + j) + a.y * __ldg(w1 + EEMB + j)
                    + a.z * __ldg(w1 + 2 * EEMB + j) + a.w * __ldg(w1 + 3 * EEMB + j);
    g_hid[(size_t)e * EEMB + j] = __uint_as_float(tf32r(gelu_f(t)));
}

// ---------------------------------------------------------------------------
// tf32 mma.sync GEMM, higher-occupancy tiling:
//   BM=64, BN=128, BK=16; 256 threads = 8 warps, warp-tile 32x32.
//   acc 32 regs/thread -> 3 blocks/SM (24 warps) via __launch_bounds__(256,3).
//   cp.async double-buffered pipeline (structure proven in R8-R10).
//   A fragments cvt.rna at read; weights pre-rounded -> raw.
// ---------------------------------------------------------------------------
template<int ACT>
__global__ void __launch_bounds__(256, 3) mma_gemm_k(
    int Aid, int wOff, const float* __restrict__ bias,
    int resId, int dupId, int Cid, float* __restrict__ Cext,
    int K, int ldW, int ldC)
{
    __shared__ float As[2][64][20];    // stride 20: banks 20g+tq distinct
    __shared__ float Bs[2][16][136];   // proven conflict-free layout

    const float* __restrict__ A = bufsel(Aid);
    const float* __restrict__ W = g_wt + wOff;
    float* __restrict__ C = Cext ? Cext : bufsel(Cid);

    const int tid  = threadIdx.x;
    const int bm   = blockIdx.x * 64;
    const int bn   = blockIdx.y * 128;
    const int w    = tid >> 5;
    const int lane = tid & 31;
    const int g    = lane >> 2;
    const int tq   = lane & 3;
    const int wm   = (w & 1) * 32;     // 2 warps along M
    const int wn   = (w >> 1) * 32;    // 4 warps along N

    // loaders: A 1 x cp16/thread, B 2 x cp16/thread per tile
    const int ar  = tid & 63;
    const int ak0 = tid >> 6;          // 0..3
    const int bk0 = tid >> 5;          // 0..7
    const int bq  = (tid & 31) * 4;

    const float* Ag  = A + (size_t)(bm + ar) * K + ak0 * 4;
    const float* Wg0 = W + (size_t)bk0 * ldW + bn + bq;
    const float* Wg1 = W + (size_t)(bk0 + 8) * ldW + bn + bq;

    unsigned dA[2], dB0[2], dB1[2];
#pragma unroll
    for (int s = 0; s < 2; s++) {
        dA[s]  = (unsigned)__cvta_generic_to_shared(&As[s][ar][ak0 * 4]);
        dB0[s] = (unsigned)__cvta_generic_to_shared(&Bs[s][bk0][bq]);
        dB1[s] = (unsigned)__cvta_generic_to_shared(&Bs[s][bk0 + 8][bq]);
    }

    float acc[2][4][4];
#pragma unroll
    for (int mi = 0; mi < 2; mi++)
#pragma unroll
        for (int ni = 0; ni < 4; ni++)
#pragma unroll
            for (int r = 0; r < 4; r++) acc[mi][ni][r] = 0.f;

    cp16(dA[0], Ag);
    cp16(dB0[0], Wg0);
    cp16(dB1[0], Wg1);
    asm volatile("cp.async.commit_group;" ::: "memory");

    const int niter = K / 16;
    for (int it = 0; it < niter; it++) {
        const int cur = it & 1;
        if (it + 1 < niter) {
            const int nxt = (it + 1) & 1;
            const int k0  = (it + 1) * 16;
            cp16(dA[nxt], Ag + k0);
            cp16(dB0[nxt], Wg0 + (size_t)k0 * ldW);
            cp16(dB1[nxt], Wg1 + (size_t)k0 * ldW);
            asm volatile("cp.async.commit_group;" ::: "memory");
            asm volatile("cp.async.wait_group 1;" ::: "memory");
        } else {
            asm volatile("cp.async.wait_group 0;" ::: "memory");
        }
        __syncthreads();

#pragma unroll
        for (int kb2 = 0; kb2 < 2; kb2++) {
            const int kb = kb2 * 8;
            unsigned a[2][4], b[4][2];
#pragma unroll
            for (int mi = 0; mi < 2; mi++) {
                const int m0 = wm + mi * 16 + g;
                a[mi][0] = tf32r(As[cur][m0][kb + tq]);
                a[mi][1] = tf32r(As[cur][m0 + 8][kb + tq]);
                a[mi][2] = tf32r(As[cur][m0][kb + tq + 4]);
                a[mi][3] = tf32r(As[cur][m0 + 8][kb + tq + 4]);
            }
#pragma unroll
            for (int ni = 0; ni < 4; ni++) {
                const int n0 = wn + ni * 8 + g;
                b[ni][0] = __float_as_uint(Bs[cur][kb + tq][n0]);
                b[ni][1] = __float_as_uint(Bs[cur][kb + tq + 4][n0]);
            }
#pragma unroll
            for (int mi = 0; mi < 2; mi++)
#pragma unroll
                for (int ni = 0; ni < 4; ni++)
                    mma_tf32(acc[mi][ni], a[mi], b[ni]);
        }
        __syncthreads();
    }

    const float* res = (resId >= 0) ? bufsel(resId) : nullptr;
    float* dup = (dupId >= 0) ? bufsel(dupId) : nullptr;
#pragma unroll
    for (int mi = 0; mi < 2; mi++) {
#pragma unroll
        for (int h = 0; h < 2; h++) {
            const int row = bm + wm + mi * 16 + g + h * 8;
#pragma unroll
            for (int ni = 0; ni < 4; ni++) {
                const int c = bn + wn + ni * 8 + tq * 2;
                float v0 = acc[mi][ni][h * 2 + 0];
                float v1 = acc[mi][ni][h * 2 + 1];
                if (bias) {
                    float2 bb = *(const float2*)(bias + c);
                    v0 += bb.x; v1 += bb.y;
                }
                if (ACT == 1) { v0 = gelu_f(v0); v1 = gelu_f(v1); }
                const size_t off = (size_t)row * ldC + c;
                if (res) {
                    float2 r = *(const float2*)(res + off);
                    v0 += r.x; v1 += r.y;
                }
                if (dup) {   // copy A row slice (K == ldC layouts match)
                    const size_t offA = (size_t)row * K + c;
                    *(float2*)(dup + offA) = *(const float2*)(A + offA);
                }
                float2 o; o.x = v0; o.y = v1;
                *(float2*)(C + off) = o;
            }
        }
    }
}

// ---------------------------------------------------------------------------
// FUSED edge GEMM + scatter, same 64x128 tiling. K = EEMB = 128.
// v4 red epilogue via lane^1 butterfly (proven R9/R10).
// ---------------------------------------------------------------------------
__global__ void __launch_bounds__(256, 3) mma_edge_k(
    int wOff, const int* __restrict__ ei, int Cid)
{
    __shared__ float As[2][64][20];
    __shared__ float Bs[2][16][136];
    __shared__ int sSrc[64], sDst[64];

    const float* __restrict__ A = g_e;
    const float* __restrict__ W = g_wt + wOff;
    float* __restrict__ C = bufsel(Cid);

    const int tid  = threadIdx.x;
    const int bm   = blockIdx.x * 64;
    const int bn   = blockIdx.y * 128;
    const int w    = tid >> 5;
    const int lane = tid & 31;
    const int g    = lane >> 2;
    const int tq   = lane & 3;
    const int wm   = (w & 1) * 32;
    const int wn   = (w >> 1) * 32;

    if (tid < 64) {
        sSrc[tid] = ei[bm + tid];
        sDst[tid] = ei[NE + bm + tid];
    }

    const int ar  = tid & 63;
    const int ak0 = tid >> 6;
    const int bk0 = tid >> 5;
    const int bq  = (tid & 31) * 4;

    const float* Ag  = A + (size_t)(bm + ar) * EEMB + ak0 * 4;
    const float* Wg0 = W + (size_t)bk0 * DIM + bn + bq;
    const float* Wg1 = W + (size_t)(bk0 + 8) * DIM + bn + bq;

    unsigned dA[2], dB0[2], dB1[2];
#pragma unroll
    for (int s = 0; s < 2; s++) {
        dA[s]  = (unsigned)__cvta_generic_to_shared(&As[s][ar][ak0 * 4]);
        dB0[s] = (unsigned)__cvta_generic_to_shared(&Bs[s][bk0][bq]);
        dB1[s] = (unsigned)__cvta_generic_to_shared(&Bs[s][bk0 + 8][bq]);
    }

    float acc[2][4][4];
#pragma unroll
    for (int mi = 0; mi < 2; mi++)
#pragma unroll
        for (int ni = 0; ni < 4; ni++)
#pragma unroll
            for (int r = 0; r < 4; r++) acc[mi][ni][r] = 0.f;

    cp16(dA[0], Ag);
    cp16(dB0[0], Wg0);
    cp16(dB1[0], Wg1);
    asm volatile("cp.async.commit_group;" ::: "memory");

    const int niter = EEMB / 16;   // 8
    for (int it = 0; it < niter; it++) {
        const int cur = it & 1;
        if (it + 1 < niter) {
            const int nxt = (it + 1) & 1;
            const int k0  = (it + 1) * 16;
            cp16(dA[nxt], Ag + k0);
            cp16(dB0[nxt], Wg0 + (size_t)k0 * DIM);
            cp16(dB1[nxt], Wg1 + (size_t)k0 * DIM);
            asm volatile("cp.async.commit_group;" ::: "memory");
            asm volatile("cp.async.wait_group 1;" ::: "memory");
        } else {
            asm volatile("cp.async.wait_group 0;" ::: "memory");
        }
        __syncthreads();

#pragma unroll
        for (int kb2 = 0; kb2 < 2; kb2++) {
            const int kb = kb2 * 8;
            unsigned a[2][4], b[4][2];
#pragma unroll
            for (int mi = 0; mi < 2; mi++) {
                const int m0 = wm + mi * 16 + g;
                a[mi][0] = tf32r(As[cur][m0][kb + tq]);
                a[mi][1] = tf32r(As[cur][m0 + 8][kb + tq]);
                a[mi][2] = tf32r(As[cur][m0][kb + tq + 4]);
                a[mi][3] = tf32r(As[cur][m0 + 8][kb + tq + 4]);
            }
#pragma unroll
            for (int ni = 0; ni < 4; ni++) {
                const int n0 = wn + ni * 8 + g;
                b[ni][0] = __float_as_uint(Bs[cur][kb + tq][n0]);
                b[ni][1] = __float_as_uint(Bs[cur][kb + tq + 4][n0]);
            }
#pragma unroll
            for (int mi = 0; mi < 2; mi++)
#pragma unroll
                for (int ni = 0; ni < 4; ni++)
                    mma_tf32(acc[mi][ni], a[mi], b[ni]);
        }
        __syncthreads();   // also orders sSrc/sDst before epilogue reads
    }

    // fused scatter epilogue (v4 reductions via lane^1 butterfly)
    const bool odd = (tq & 1);
#pragma unroll
    for (int mi = 0; mi < 2; mi++) {
#pragma unroll
        for (int h = 0; h < 2; h++) {
            const int lr = wm + mi * 16 + g + h * 8;
            const int s = sSrc[lr];
            const int d = sDst[lr];
            const float* Pp = g_P + (size_t)s * DIM;
            const float* Qp = g_Q + (size_t)d * DIM;
            float* Op = C + (size_t)d * DIM;
#pragma unroll
            for (int p = 0; p < 2; p++) {
                float s0 = odd ? acc[mi][2*p][h*2+0] : acc[mi][2*p+1][h*2+0];
                float s1 = odd ? acc[mi][2*p][h*2+1] : acc[mi][2*p+1][h*2+1];
                float r0 = __shfl_xor_sync(0xffffffffu, s0, 1);
                float r1 = __shfl_xor_sync(0xffffffffu, s1, 1);
                float o0 = odd ? acc[mi][2*p+1][h*2+0] : acc[mi][2*p][h*2+0];
                float o1 = odd ? acc[mi][2*p+1][h*2+1] : acc[mi][2*p][h*2+1];
                float4 v;
                if (odd) { v.x = r0; v.y = r1; v.z = o0; v.w = o1; }
                else     { v.x = o0; v.y = o1; v.z = r0; v.w = r1; }

                const int c = bn + wn + p * 16 + (tq & 1) * 8 + (tq >> 1) * 4;
                float4 pv = *(const float4*)(Pp + c);
                float4 qv = *(const float4*)(Qp + c);
                v.x = gelu_f(v.x + pv.x + qv.x);
                v.y = gelu_f(v.y + pv.y + qv.y);
                v.z = gelu_f(v.z + pv.z + qv.z);
                v.w = gelu_f(v.w + pv.w + qv.w);

                asm volatile("red.global.add.v4.f32 [%0], {%1, %2, %3, %4};"
                             :: "l"(Op + c), "f"(v.x), "f"(v.y), "f"(v.z), "f"(v.w)
                             : "memory");
            }
        }
    }
}

// ---------------------------------------------------------------------------
extern "C" void kernel_launch(void* const* d_in, const int* in_sizes, int n_in,
                              void* d_out, int out_size)
{
    const float* x     = (const float*)d_in[0];
    const int*   ei    = (const int*)d_in[1];
    const float* attr  = (const float*)d_in[2];
    const float* ee_w1 = (const float*)d_in[3];
    const float* ee_b1 = (const float*)d_in[4];
    const float* ee_w2 = (const float*)d_in[5];
    const float* ee_b2 = (const float*)d_in[6];
    const float* ff1_w = (const float*)d_in[7];
    const float* ff1_b = (const float*)d_in[8];
    const float* mp1_w = (const float*)d_in[9];
    const float* mp1_b = (const float*)d_in[10];
    const float* mp2_w = (const float*)d_in[11];
    const float* mp2_b = (const float*)d_in[12];
    const float* ff2_w = (const float*)d_in[13];
    const float* ff2_b = (const float*)d_in[14];
    float* out = (float*)d_out;

    const int n4 = NN * DIM / 4;
    const int cb = (n4 + 255) / 256;
    const dim3 gN(NN / 64, 2);       // node GEMMs: BM=64
    const dim3 gE(NE / 64, 2);       // fused edge GEMM+scatter
    const dim3 gEE(NE / 64, 1);      // edge-embed layer-2 GEMM (N=128)

    // pre-round all weights into g_wt (tf32 RNA), [K,N] layout
    cvtw_k<<<(262144/4 + 255)/256, 256>>>(ff1_w, WOFF_FF1/4, 262144/4);
    cvtw_k<<<(655360/4 + 255)/256, 256>>>(mp1_w, WOFF_MP1/4, 655360/4);
    cvtw_k<<<(655360/4 + 255)/256, 256>>>(mp2_w, WOFF_MP2/4, 655360/4);
    cvtw_k<<<(262144/4 + 255)/256, 256>>>(ff2_w, WOFF_FF2/4, 262144/4);
    cvtw_k<<<(16384/4 + 255)/256, 256>>>(ee_w2, WOFF_EEW2/4, 16384/4);

    copy_in_k<<<cb, 256>>>(x, B_X, n4);

    // edge embedder: layer1 SIMT, layer2 GEMM
    ee1_k<<<NE / 2, 256>>>(attr, ee_w1, ee_b1);
    mma_gemm_k<0><<<gEE, 256>>>(B_HID, WOFF_EEW2, ee_b2, -1, -1, B_E, nullptr,
                                EEMB, EEMB, EEMB);

    for (int i = 0; i < DEPTH; i++) {
        const int f1o = WOFF_FF1 + i * DIM * DIM;
        const int f2o = WOFF_FF2 + i * DIM * DIM;
        const int m1o = WOFF_MP1 + i * 640 * DIM;
        const int m2o = WOFF_MP2 + i * 640 * DIM;

        // hA = gelu(x @ ff1_w + b)
        mma_gemm_k<1><<<gN, 256>>>(B_X, f1o, ff1_b + i * DIM, -1, -1, B_HA, nullptr,
                                   DIM, DIM, DIM);

        // message pass 1: hA -> hB
        mma_gemm_k<0><<<gN, 256>>>(B_HA, m1o,             mp1_b + i * DIM, -1, -1,  B_P, nullptr, DIM, DIM, DIM);
        mma_gemm_k<0><<<gN, 256>>>(B_HA, m1o + 256 * DIM, nullptr,         -1, B_HB, B_Q, nullptr, DIM, DIM, DIM);
        mma_edge_k<<<gE, 256>>>(m1o + 512 * DIM, ei, B_HB);

        // message pass 2: hB -> hA
        mma_gemm_k<0><<<gN, 256>>>(B_HB, m2o,             mp2_b + i * DIM, -1, -1,  B_P, nullptr, DIM, DIM, DIM);
        mma_gemm_k<0><<<gN, 256>>>(B_HB, m2o + 256 * DIM, nullptr,         -1, B_HA, B_Q, nullptr, DIM, DIM, DIM);
        mma_edge_k<<<gE, 256>>>(m2o + 512 * DIM, ei, B_HA);

        // x = x + hA @ ff2_w + b   (last layer writes d_out directly)
        mma_gemm_k<0><<<gN, 256>>>(B_HA, f2o, ff2_b + i * DIM, B_X, -1, B_X,
                                   (i == DEPTH - 1) ? out : nullptr, DIM, DIM, DIM);
    }
}

// round 16
// speedup vs baseline: 1.1648x; 1.0483x over previous
#include <cuda_runtime.h>
#include <math.h>

#define NN 49152
#define NE 393216
#define DIM 256
#define EEMB 128
#define DEPTH 4

// ---- scratch (static device globals; no runtime allocation) ----
__device__ float g_e[(size_t)NE * EEMB];     // edge embeddings
__device__ float g_hid[(size_t)NE * EEMB];   // edge-embed hidden layer
__device__ float g_P[(size_t)NN * DIM];      // h @ Wa + b
__device__ float g_Q[(size_t)NN * DIM];      // h @ Wb
__device__ float g_hA[(size_t)NN * DIM];
__device__ float g_hB[(size_t)NN * DIM];
__device__ float g_x[(size_t)NN * DIM];
__device__ float g_wt[1851392];              // tf32-pre-rounded weights

// weight offsets inside g_wt (floats) — [K,N] row-major, as delivered
#define WOFF_FF1  0
#define WOFF_MP1  262144
#define WOFF_MP2  917504
#define WOFF_FF2  1572864
#define WOFF_EEW2 1835008

#define B_E   0
#define B_P   2
#define B_Q   3
#define B_HA  4
#define B_HB  5
#define B_X   6
#define B_HID 7

__device__ __forceinline__ float* bufsel(int id) {
    switch (id) {
        case B_E:   return g_e;
        case B_P:   return g_P;
        case B_Q:   return g_Q;
        case B_HA:  return g_hA;
        case B_HB:  return g_hB;
        case B_HID: return g_hid;
        default:    return g_x;
    }
}

__device__ __forceinline__ float gelu_f(float v) {
    return 0.5f * v * (1.0f + erff(v * 0.70710678118654752440f));
}

__device__ __forceinline__ unsigned tf32r(float f) {
    unsigned u;
    asm("cvt.rna.tf32.f32 %0, %1;" : "=r"(u) : "f"(f));
    return u;
}

__device__ __forceinline__ void mma_tf32(float* c, const unsigned* a, const unsigned* b) {
    asm volatile(
        "mma.sync.aligned.m16n8k8.row.col.f32.tf32.tf32.f32 "
        "{%0,%1,%2,%3}, {%4,%5,%6,%7}, {%8,%9}, {%0,%1,%2,%3};\n"
        : "+f"(c[0]), "+f"(c[1]), "+f"(c[2]), "+f"(c[3])
        : "r"(a[0]), "r"(a[1]), "r"(a[2]), "r"(a[3]), "r"(b[0]), "r"(b[1]));
}

__device__ __forceinline__ void cp16(unsigned dst, const void* src) {
    asm volatile("cp.async.cg.shared.global [%0], [%1], 16;"
                 :: "r"(dst), "l"(src));
}

// ---------------------------------------------------------------------------
// weight pre-rounding (proven)
// ---------------------------------------------------------------------------
__global__ void cvtw_k(const float* __restrict__ src, int dstOff4, int n4) {
    int i = blockIdx.x * blockDim.x + threadIdx.x;
    if (i < n4) {
        float4 v = ((const float4*)src)[i];
        float4 o;
        o.x = __uint_as_float(tf32r(v.x));
        o.y = __uint_as_float(tf32r(v.y));
        o.z = __uint_as_float(tf32r(v.z));
        o.w = __uint_as_float(tf32r(v.w));
        ((float4*)g_wt)[dstOff4 + i] = o;
    }
}

__global__ void copy_in_k(const float* __restrict__ s, int did, int n4) {
    int i = blockIdx.x * blockDim.x + threadIdx.x;
    if (i < n4) ((float4*)bufsel(did))[i] = ((const float4*)s)[i];
}

// ---------------------------------------------------------------------------
// edge embedder layer 1 (proven): g_hid = round_tf32(gelu(attr @ w1 + b1))
// ---------------------------------------------------------------------------
__global__ void __launch_bounds__(256) ee1_k(
    const float* __restrict__ attr,
    const float* __restrict__ w1, const float* __restrict__ b1)
{
    const int sub = threadIdx.x >> 7;
    const int j   = threadIdx.x & 127;
    const int e   = blockIdx.x * 2 + sub;

    float4 a = *(const float4*)(attr + (size_t)e * 4);
    float t = b1[j] + a.x * __ldg(w1 + j) + a.y * __ldg(w1 + EEMB + j)
                    + a.z * __ldg(w1 + 2 * EEMB + j) + a.w * __ldg(w1 + 3 * EEMB + j);
    g_hid[(size_t)e * EEMB + j] = __uint_as_float(tf32r(gelu_f(t)));
}

// ---------------------------------------------------------------------------
// tf32 mma.sync GEMM, max-occupancy tiling:
//   BM=64, BN=128, BK=16; 256 threads = 8 warps, warp-tile 32x32.
//   acc 32 regs/thread -> 4 blocks/SM (32 warps) via __launch_bounds__(256,4).
//   cp.async double-buffered pipeline (structure proven in R8-R15).
//   A fragments cvt.rna at read; weights pre-rounded -> raw.
// ---------------------------------------------------------------------------
template<int ACT>
__global__ void __launch_bounds__(256, 4) mma_gemm_k(
    int Aid, int wOff, const float* __restrict__ bias,
    int resId, int dupId, int Cid, float* __restrict__ Cext,
    int K, int ldW, int ldC)
{
    __shared__ float As[2][64][20];    // stride 20: banks 20g+tq distinct
    __shared__ float Bs[2][16][136];   // proven conflict-free layout

    const float* __restrict__ A = bufsel(Aid);
    const float* __restrict__ W = g_wt + wOff;
    float* __restrict__ C = Cext ? Cext : bufsel(Cid);

    const int tid  = threadIdx.x;
    const int bm   = blockIdx.x * 64;
    const int bn   = blockIdx.y * 128;
    const int w    = tid >> 5;
    const int lane = tid & 31;
    const int g    = lane >> 2;
    const int tq   = lane & 3;
    const int wm   = (w & 1) * 32;     // 2 warps along M
    const int wn   = (w >> 1) * 32;    // 4 warps along N

    // loaders: A 1 x cp16/thread, B 2 x cp16/thread per tile
    const int ar  = tid & 63;
    const int ak0 = tid >> 6;          // 0..3
    const int bk0 = tid >> 5;          // 0..7
    const int bq  = (tid & 31) * 4;

    const float* Ag  = A + (size_t)(bm + ar) * K + ak0 * 4;
    const float* Wg0 = W + (size_t)bk0 * ldW + bn + bq;
    const float* Wg1 = W + (size_t)(bk0 + 8) * ldW + bn + bq;

    unsigned dA[2], dB0[2], dB1[2];
#pragma unroll
    for (int s = 0; s < 2; s++) {
        dA[s]  = (unsigned)__cvta_generic_to_shared(&As[s][ar][ak0 * 4]);
        dB0[s] = (unsigned)__cvta_generic_to_shared(&Bs[s][bk0][bq]);
        dB1[s] = (unsigned)__cvta_generic_to_shared(&Bs[s][bk0 + 8][bq]);
    }

    float acc[2][4][4];
#pragma unroll
    for (int mi = 0; mi < 2; mi++)
#pragma unroll
        for (int ni = 0; ni < 4; ni++)
#pragma unroll
            for (int r = 0; r < 4; r++) acc[mi][ni][r] = 0.f;

    cp16(dA[0], Ag);
    cp16(dB0[0], Wg0);
    cp16(dB1[0], Wg1);
    asm volatile("cp.async.commit_group;" ::: "memory");

    const int niter = K / 16;
    for (int it = 0; it < niter; it++) {
        const int cur = it & 1;
        if (it + 1 < niter) {
            const int nxt = (it + 1) & 1;
            const int k0  = (it + 1) * 16;
            cp16(dA[nxt], Ag + k0);
            cp16(dB0[nxt], Wg0 + (size_t)k0 * ldW);
            cp16(dB1[nxt], Wg1 + (size_t)k0 * ldW);
            asm volatile("cp.async.commit_group;" ::: "memory");
            asm volatile("cp.async.wait_group 1;" ::: "memory");
        } else {
            asm volatile("cp.async.wait_group 0;" ::: "memory");
        }
        __syncthreads();

#pragma unroll
        for (int kb2 = 0; kb2 < 2; kb2++) {
            const int kb = kb2 * 8;
            unsigned a[2][4], b[4][2];
#pragma unroll
            for (int mi = 0; mi < 2; mi++) {
                const int m0 = wm + mi * 16 + g;
                a[mi][0] = tf32r(As[cur][m0][kb + tq]);
                a[mi][1] = tf32r(As[cur][m0 + 8][kb + tq]);
                a[mi][2] = tf32r(As[cur][m0][kb + tq + 4]);
                a[mi][3] = tf32r(As[cur][m0 + 8][kb + tq + 4]);
            }
#pragma unroll
            for (int ni = 0; ni < 4; ni++) {
                const int n0 = wn + ni * 8 + g;
                b[ni][0] = __float_as_uint(Bs[cur][kb + tq][n0]);
                b[ni][1] = __float_as_uint(Bs[cur][kb + tq + 4][n0]);
            }
#pragma unroll
            for (int mi = 0; mi < 2; mi++)
#pragma unroll
                for (int ni = 0; ni < 4; ni++)
                    mma_tf32(acc[mi][ni], a[mi], b[ni]);
        }
        __syncthreads();
    }

    const float* res = (resId >= 0) ? bufsel(resId) : nullptr;
    float* dup = (dupId >= 0) ? bufsel(dupId) : nullptr;
#pragma unroll
    for (int mi = 0; mi < 2; mi++) {
#pragma unroll
        for (int h = 0; h < 2; h++) {
            const int row = bm + wm + mi * 16 + g + h * 8;
#pragma unroll
            for (int ni = 0; ni < 4; ni++) {
                const int c = bn + wn + ni * 8 + tq * 2;
                float v0 = acc[mi][ni][h * 2 + 0];
                float v1 = acc[mi][ni][h * 2 + 1];
                if (bias) {
                    float2 bb = *(const float2*)(bias + c);
                    v0 += bb.x; v1 += bb.y;
                }
                if (ACT == 1) { v0 = gelu_f(v0); v1 = gelu_f(v1); }
                const size_t off = (size_t)row * ldC + c;
                if (res) {
                    float2 r = *(const float2*)(res + off);
                    v0 += r.x; v1 += r.y;
                }
                if (dup) {   // copy A row slice (K == ldC layouts match)
                    const size_t offA = (size_t)row * K + c;
                    *(float2*)(dup + offA) = *(const float2*)(A + offA);
                }
                float2 o; o.x = v0; o.y = v1;
                *(float2*)(C + off) = o;
            }
        }
    }
}

// ---------------------------------------------------------------------------
// FUSED edge GEMM + scatter, same 64x128 tiling. K = EEMB = 128.
// v4 red epilogue via lane^1 butterfly (proven R9-R15).
// ---------------------------------------------------------------------------
__global__ void __launch_bounds__(256, 4) mma_edge_k(
    int wOff, const int* __restrict__ ei, int Cid)
{
    __shared__ float As[2][64][20];
    __shared__ float Bs[2][16][136];
    __shared__ int sSrc[64], sDst[64];

    const float* __restrict__ A = g_e;
    const float* __restrict__ W = g_wt + wOff;
    float* __restrict__ C = bufsel(Cid);

    const int tid  = threadIdx.x;
    const int bm   = blockIdx.x * 64;
    const int bn   = blockIdx.y * 128;
    const int w    = tid >> 5;
    const int lane = tid & 31;
    const int g    = lane >> 2;
    const int tq   = lane & 3;
    const int wm   = (w & 1) * 32;
    const int wn   = (w >> 1) * 32;

    if (tid < 64) {
        sSrc[tid] = ei[bm + tid];
        sDst[tid] = ei[NE + bm + tid];
    }

    const int ar  = tid & 63;
    const int ak0 = tid >> 6;
    const int bk0 = tid >> 5;
    const int bq  = (tid & 31) * 4;

    const float* Ag  = A + (size_t)(bm + ar) * EEMB + ak0 * 4;
    const float* Wg0 = W + (size_t)bk0 * DIM + bn + bq;
    const float* Wg1 = W + (size_t)(bk0 + 8) * DIM + bn + bq;

    unsigned dA[2], dB0[2], dB1[2];
#pragma unroll
    for (int s = 0; s < 2; s++) {
        dA[s]  = (unsigned)__cvta_generic_to_shared(&As[s][ar][ak0 * 4]);
        dB0[s] = (unsigned)__cvta_generic_to_shared(&Bs[s][bk0][bq]);
        dB1[s] = (unsigned)__cvta_generic_to_shared(&Bs[s][bk0 + 8][bq]);
    }

    float acc[2][4][4];
#pragma unroll
    for (int mi = 0; mi < 2; mi++)
#pragma unroll
        for (int ni = 0; ni < 4; ni++)
#pragma unroll
            for (int r = 0; r < 4; r++) acc[mi][ni][r] = 0.f;

    cp16(dA[0], Ag);
    cp16(dB0[0], Wg0);
    cp16(dB1[0], Wg1);
    asm volatile("cp.async.commit_group;" ::: "memory");

    const int niter = EEMB / 16;   // 8
    for (int it = 0; it < niter; it++) {
        const int cur = it & 1;
        if (it + 1 < niter) {
            const int nxt = (it + 1) & 1;
            const int k0  = (it + 1) * 16;
            cp16(dA[nxt], Ag + k0);
            cp16(dB0[nxt], Wg0 + (size_t)k0 * DIM);
            cp16(dB1[nxt], Wg1 + (size_t)k0 * DIM);
            asm volatile("cp.async.commit_group;" ::: "memory");
            asm volatile("cp.async.wait_group 1;" ::: "memory");
        } else {
            asm volatile("cp.async.wait_group 0;" ::: "memory");
        }
        __syncthreads();

#pragma unroll
        for (int kb2 = 0; kb2 < 2; kb2++) {
            const int kb = kb2 * 8;
            unsigned a[2][4], b[4][2];
#pragma unroll
            for (int mi = 0; mi < 2; mi++) {
                const int m0 = wm + mi * 16 + g;
                a[mi][0] = tf32r(As[cur][m0][kb + tq]);
                a[mi][1] = tf32r(As[cur][m0 + 8][kb + tq]);
                a[mi][2] = tf32r(As[cur][m0][kb + tq + 4]);
                a[mi][3] = tf32r(As[cur][m0 + 8][kb + tq + 4]);
            }
#pragma unroll
            for (int ni = 0; ni < 4; ni++) {
                const int n0 = wn + ni * 8 + g;
                b[ni][0] = __float_as_uint(Bs[cur][kb + tq][n0]);
                b[ni][1] = __float_as_uint(Bs[cur][kb + tq + 4][n0]);
            }
#pragma unroll
            for (int mi = 0; mi < 2; mi++)
#pragma unroll
                for (int ni = 0; ni < 4; ni++)
                    mma_tf32(acc[mi][ni], a[mi], b[ni]);
        }
        __syncthreads();   // also orders sSrc/sDst before epilogue reads
    }

    // fused scatter epilogue (v4 reductions via lane^1 butterfly)
    const bool odd = (tq & 1);
#pragma unroll
    for (int mi = 0; mi < 2; mi++) {
#pragma unroll
        for (int h = 0; h < 2; h++) {
            const int lr = wm + mi * 16 + g + h * 8;
            const int s = sSrc[lr];
            const int d = sDst[lr];
            const float* Pp = g_P + (size_t)s * DIM;
            const float* Qp = g_Q + (size_t)d * DIM;
            float* Op = C + (size_t)d * DIM;
#pragma unroll
            for (int p = 0; p < 2; p++) {
                float s0 = odd ? acc[mi][2*p][h*2+0] : acc[mi][2*p+1][h*2+0];
                float s1 = odd ? acc[mi][2*p][h*2+1] : acc[mi][2*p+1][h*2+1];
                float r0 = __shfl_xor_sync(0xffffffffu, s0, 1);
                float r1 = __shfl_xor_sync(0xffffffffu, s1, 1);
                float o0 = odd ? acc[mi][2*p+1][h*2+0] : acc[mi][2*p][h*2+0];
                float o1 = odd ? acc[mi][2*p+1][h*2+1] : acc[mi][2*p][h*2+1];
                float4 v;
                if (odd) { v.x = r0; v.y = r1; v.z = o0; v.w = o1; }
                else     { v.x = o0; v.y = o1; v.z = r0; v.w = r1; }

                const int c = bn + wn + p * 16 + (tq & 1) * 8 + (tq >> 1) * 4;
                float4 pv = *(const float4*)(Pp + c);
                float4 qv = *(const float4*)(Qp + c);
                v.x = gelu_f(v.x + pv.x + qv.x);
                v.y = gelu_f(v.y + pv.y + qv.y);
                v.z = gelu_f(v.z + pv.z + qv.z);
                v.w = gelu_f(v.w + pv.w + qv.w);

                asm volatile("red.global.add.v4.f32 [%0], {%1, %2, %3, %4};"
                             :: "l"(Op + c), "f"(v.x), "f"(v.y), "f"(v.z), "f"(v.w)
                             : "memory");
            }
        }
    }
}

// ---------------------------------------------------------------------------
extern "C" void kernel_launch(void* const* d_in, const int* in_sizes, int n_in,
                              void* d_out, int out_size)
{
    const float* x     = (const float*)d_in[0];
    const int*   ei    = (const int*)d_in[1];
    const float* attr  = (const float*)d_in[2];
    const float* ee_w1 = (const float*)d_in[3];
    const float* ee_b1 = (const float*)d_in[4];
    const float* ee_w2 = (const float*)d_in[5];
    const float* ee_b2 = (const float*)d_in[6];
    const float* ff1_w = (const float*)d_in[7];
    const float* ff1_b = (const float*)d_in[8];
    const float* mp1_w = (const float*)d_in[9];
    const float* mp1_b = (const float*)d_in[10];
    const float* mp2_w = (const float*)d_in[11];
    const float* mp2_b = (const float*)d_in[12];
    const float* ff2_w = (const float*)d_in[13];
    const float* ff2_b = (const float*)d_in[14];
    float* out = (float*)d_out;

    const int n4 = NN * DIM / 4;
    const int cb = (n4 + 255) / 256;
    const dim3 gN(NN / 64, 2);       // node GEMMs: BM=64
    const dim3 gE(NE / 64, 2);       // fused edge GEMM+scatter
    const dim3 gEE(NE / 64, 1);      // edge-embed layer-2 GEMM (N=128)

    // pre-round all weights into g_wt (tf32 RNA), [K,N] layout
    cvtw_k<<<(262144/4 + 255)/256, 256>>>(ff1_w, WOFF_FF1/4, 262144/4);
    cvtw_k<<<(655360/4 + 255)/256, 256>>>(mp1_w, WOFF_MP1/4, 655360/4);
    cvtw_k<<<(655360/4 + 255)/256, 256>>>(mp2_w, WOFF_MP2/4, 655360/4);
    cvtw_k<<<(262144/4 + 255)/256, 256>>>(ff2_w, WOFF_FF2/4, 262144/4);
    cvtw_k<<<(16384/4 + 255)/256, 256>>>(ee_w2, WOFF_EEW2/4, 16384/4);

    copy_in_k<<<cb, 256>>>(x, B_X, n4);

    // edge embedder: layer1 SIMT, layer2 GEMM
    ee1_k<<<NE / 2, 256>>>(attr, ee_w1, ee_b1);
    mma_gemm_k<0><<<gEE, 256>>>(B_HID, WOFF_EEW2, ee_b2, -1, -1, B_E, nullptr,
                                EEMB, EEMB, EEMB);

    for (int i = 0; i < DEPTH; i++) {
        const int f1o = WOFF_FF1 + i * DIM * DIM;
        const int f2o = WOFF_FF2 + i * DIM * DIM;
        const int m1o = WOFF_MP1 + i * 640 * DIM;
        const int m2o = WOFF_MP2 + i * 640 * DIM;

        // hA = gelu(x @ ff1_w + b)
        mma_gemm_k<1><<<gN, 256>>>(B_X, f1o, ff1_b + i * DIM, -1, -1, B_HA, nullptr,
                                   DIM, DIM, DIM);

        // message pass 1: hA -> hB
        mma_gemm_k<0><<<gN, 256>>>(B_HA, m1o,             mp1_b + i * DIM, -1, -1,  B_P, nullptr, DIM, DIM, DIM);
        mma_gemm_k<0><<<gN, 256>>>(B_HA, m1o + 256 * DIM, nullptr,         -1, B_HB, B_Q, nullptr, DIM, DIM, DIM);
        mma_edge_k<<<gE, 256>>>(m1o + 512 * DIM, ei, B_HB);

        // message pass 2: hB -> hA
        mma_gemm_k<0><<<gN, 256>>>(B_HB, m2o,             mp2_b + i * DIM, -1, -1,  B_P, nullptr, DIM, DIM, DIM);
        mma_gemm_k<0><<<gN, 256>>>(B_HB, m2o + 256 * DIM, nullptr,         -1, B_HA, B_Q, nullptr, DIM, DIM, DIM);
        mma_edge_k<<<gE, 256>>>(m2o + 512 * DIM, ei, B_HA);

        // x = x + hA @ ff2_w + b   (last layer writes d_out directly)
        mma_gemm_k<0><<<gN, 256>>>(B_HA, f2o, ff2_b + i * DIM, B_X, -1, B_X,
                                   (i == DEPTH - 1) ? out : nullptr, DIM, DIM, DIM);
    }
}

// round 17
// speedup vs baseline: 1.3647x; 1.1716x over previous
#include <cuda_runtime.h>
#include <cuda_fp16.h>
#include <math.h>

#define NN 49152
#define NE 393216
#define DIM 256
#define EEMB 128
#define DEPTH 4

// ---- scratch (static device globals; no runtime allocation) ----
__device__ float  g_P[(size_t)NN * DIM];      // h @ Wa + b (fp32)
__device__ float  g_Q[(size_t)NN * DIM];      // h @ Wb     (fp32)
__device__ float  g_hA[(size_t)NN * DIM];
__device__ float  g_hB[(size_t)NN * DIM];
__device__ float  g_x[(size_t)NN * DIM];
__device__ __half g_a16[(size_t)NN * DIM];    // fp16 copy of dirty activations
__device__ __half g_h16[(size_t)NN * DIM];    // fp16 copy of clean hA
__device__ __half g_e16[(size_t)NE * EEMB];   // edge embeddings (fp16)
__device__ __half g_hid16[(size_t)NE * EEMB]; // edge-embed hidden (fp16)
__device__ __half g_wt16[1851392];            // transposed fp16 weights [N][K]

// transposed weight offsets (elements)
#define WT_FF1(i) ((i)*65536)
#define WT_A1(i)  (262144 + (i)*65536)
#define WT_B1(i)  (524288 + (i)*65536)
#define WT_C1(i)  (786432 + (i)*32768)
#define WT_A2(i)  (917504 + (i)*65536)
#define WT_B2(i)  (1179648 + (i)*65536)
#define WT_C2(i)  (1441792 + (i)*32768)
#define WT_FF2(i) (1572864 + (i)*65536)
#define WT_EE2    1835008

// fp32 buffer ids
#define B_P   2
#define B_Q   3
#define B_HA  4
#define B_HB  5
#define B_X   6
// fp16 buffer ids
#define H_A16  0
#define H_H16  1
#define H_E16  2
#define H_HID  3

__device__ __forceinline__ float* bufsel(int id) {
    switch (id) {
        case B_P:  return g_P;
        case B_Q:  return g_Q;
        case B_HA: return g_hA;
        case B_HB: return g_hB;
        default:   return g_x;
    }
}
__device__ __forceinline__ __half* bufsel16(int id) {
    switch (id) {
        case H_A16: return g_a16;
        case H_H16: return g_h16;
        case H_E16: return g_e16;
        default:    return g_hid16;
    }
}

__device__ __forceinline__ float gelu_f(float v) {
    return 0.5f * v * (1.0f + erff(v * 0.70710678118654752440f));
}

__device__ __forceinline__ void mma_f16(float* c, const unsigned* a, const unsigned* b) {
    asm volatile(
        "mma.sync.aligned.m16n8k16.row.col.f32.f16.f16.f32 "
        "{%0,%1,%2,%3}, {%4,%5,%6,%7}, {%8,%9}, {%0,%1,%2,%3};\n"
        : "+f"(c[0]), "+f"(c[1]), "+f"(c[2]), "+f"(c[3])
        : "r"(a[0]), "r"(a[1]), "r"(a[2]), "r"(a[3]), "r"(b[0]), "r"(b[1]));
}

__device__ __forceinline__ void cp16(unsigned dst, const void* src) {
    asm volatile("cp.async.cg.shared.global [%0], [%1], 16;"
                 :: "r"(dst), "l"(src));
}

// ---------------------------------------------------------------------------
// weight transpose + fp16 convert: g_wt16[dst + n*K + k] = h(src[k*N + n])
// ---------------------------------------------------------------------------
__global__ void cvtwt16_k(const float* __restrict__ src, int dstOff, int K, int N) {
    int idx = blockIdx.x * 256 + threadIdx.x;
    if (idx < N * K) {
        int n = idx / K, k = idx % K;
        g_wt16[dstOff + idx] = __float2half_rn(src[(size_t)k * N + n]);
    }
}

// fp32 buffer -> g_a16 (fp16)
__global__ void cvt16_k(int sid, int n4) {
    int i = blockIdx.x * blockDim.x + threadIdx.x;
    if (i < n4) {
        float4 v = ((const float4*)bufsel(sid))[i];
        __half2 lo = __floats2half2_rn(v.x, v.y);
        __half2 hi = __floats2half2_rn(v.z, v.w);
        uint2 o;
        o.x = *(unsigned*)&lo;
        o.y = *(unsigned*)&hi;
        ((uint2*)g_a16)[i] = o;
    }
}

__global__ void copy_in_k(const float* __restrict__ s, int n4) {
    int i = blockIdx.x * blockDim.x + threadIdx.x;
    if (i < n4) ((float4*)g_x)[i] = ((const float4*)s)[i];
}

// ---------------------------------------------------------------------------
// edge embedder layer 1: g_hid16 = h(gelu(attr @ w1 + b1))
// ---------------------------------------------------------------------------
__global__ void __launch_bounds__(256) ee1_k(
    const float* __restrict__ attr,
    const float* __restrict__ w1, const float* __restrict__ b1)
{
    const int sub = threadIdx.x >> 7;
    const int j   = threadIdx.x & 127;
    const int e   = blockIdx.x * 2 + sub;

    float4 a = *(const float4*)(attr + (size_t)e * 4);
    float t = b1[j] + a.x * __ldg(w1 + j) + a.y * __ldg(w1 + EEMB + j)
                    + a.z * __ldg(w1 + 2 * EEMB + j) + a.w * __ldg(w1 + 3 * EEMB + j);
    g_hid16[(size_t)e * EEMB + j] = __float2half_rn(gelu_f(t));
}

// ---------------------------------------------------------------------------
// fp16 mma GEMM: BM=64, BN=128, BK=16; 8 warps, warp-tile 32x32 (m16n8k16).
// A fp16 [M][K]; W fp16 [N][K] (transposed). acc fp32.
// SMEM tiles stride 24 halves (48B): frag banks 12g+tq all distinct.
// Epilogue: C = act(acc + bias)[+res]; optional fp32 dup copy; optional fp16 out.
// ---------------------------------------------------------------------------
template<int ACT>
__global__ void __launch_bounds__(256, 4) mma_gemm_k(
    int A16id, int wOff, const float* __restrict__ bias,
    int resId, int dupSrcId, int dupDstId,
    int Cid, float* __restrict__ Cext, int C16id,
    int K, int ldC)
{
    __shared__ __half As[2][64][24];
    __shared__ __half Bs[2][128][24];

    const __half* __restrict__ A = bufsel16(A16id);
    const __half* __restrict__ W = g_wt16 + wOff;
    float* __restrict__ C = Cext ? Cext : ((Cid >= 0) ? bufsel(Cid) : nullptr);
    __half* __restrict__ C16 = (C16id >= 0) ? bufsel16(C16id) : nullptr;

    const int tid  = threadIdx.x;
    const int bm   = blockIdx.x * 64;
    const int bn   = blockIdx.y * 128;
    const int w    = tid >> 5;
    const int lane = tid & 31;
    const int g    = lane >> 2;
    const int tq   = lane & 3;
    const int wm   = (w & 1) * 32;
    const int wn   = (w >> 1) * 32;

    // loaders: A (tid<128): row=tid>>1, half=tid&1 ; B (all): row=tid>>1, half=tid&1
    const int lrow = tid >> 1;        // 0..127
    const int lhf  = tid & 1;         // 0..1

    const __half* Ag = A + (size_t)(bm + (lrow & 63)) * K + lhf * 8;
    const __half* Bg = W + (size_t)(bn + lrow) * K + lhf * 8;

    unsigned dA[2], dB[2];
#pragma unroll
    for (int s = 0; s < 2; s++) {
        dA[s] = (unsigned)__cvta_generic_to_shared(&As[s][lrow & 63][lhf * 8]);
        dB[s] = (unsigned)__cvta_generic_to_shared(&Bs[s][lrow][lhf * 8]);
    }
    const bool doA = (tid < 128);

    float acc[2][4][4];
#pragma unroll
    for (int mi = 0; mi < 2; mi++)
#pragma unroll
        for (int ni = 0; ni < 4; ni++)
#pragma unroll
            for (int r = 0; r < 4; r++) acc[mi][ni][r] = 0.f;

    if (doA) cp16(dA[0], Ag);
    cp16(dB[0], Bg);
    asm volatile("cp.async.commit_group;" ::: "memory");

    const int niter = K / 16;
    for (int it = 0; it < niter; it++) {
        const int cur = it & 1;
        if (it + 1 < niter) {
            const int nxt = (it + 1) & 1;
            const int k0  = (it + 1) * 16;
            if (doA) cp16(dA[nxt], Ag + k0);
            cp16(dB[nxt], Bg + k0);
            asm volatile("cp.async.commit_group;" ::: "memory");
            asm volatile("cp.async.wait_group 1;" ::: "memory");
        } else {
            asm volatile("cp.async.wait_group 0;" ::: "memory");
        }
        __syncthreads();

        unsigned a[2][4], b[4][2];
#pragma unroll
        for (int mi = 0; mi < 2; mi++) {
            const int m0 = wm + mi * 16 + g;
            a[mi][0] = *(const unsigned*)&As[cur][m0][2 * tq];
            a[mi][1] = *(const unsigned*)&As[cur][m0 + 8][2 * tq];
            a[mi][2] = *(const unsigned*)&As[cur][m0][2 * tq + 8];
            a[mi][3] = *(const unsigned*)&As[cur][m0 + 8][2 * tq + 8];
        }
#pragma unroll
        for (int ni = 0; ni < 4; ni++) {
            const int n0 = wn + ni * 8 + g;
            b[ni][0] = *(const unsigned*)&Bs[cur][n0][2 * tq];
            b[ni][1] = *(const unsigned*)&Bs[cur][n0][2 * tq + 8];
        }
#pragma unroll
        for (int mi = 0; mi < 2; mi++)
#pragma unroll
            for (int ni = 0; ni < 4; ni++)
                mma_f16(acc[mi][ni], a[mi], b[ni]);
        __syncthreads();
    }

    const float* res = (resId >= 0) ? bufsel(resId) : nullptr;
    const float* dupS = (dupSrcId >= 0) ? bufsel(dupSrcId) : nullptr;
    float* dupD = (dupDstId >= 0) ? bufsel(dupDstId) : nullptr;
#pragma unroll
    for (int mi = 0; mi < 2; mi++) {
#pragma unroll
        for (int h = 0; h < 2; h++) {
            const int row = bm + wm + mi * 16 + g + h * 8;
#pragma unroll
            for (int ni = 0; ni < 4; ni++) {
                const int c = bn + wn + ni * 8 + tq * 2;
                float v0 = acc[mi][ni][h * 2 + 0];
                float v1 = acc[mi][ni][h * 2 + 1];
                if (bias) {
                    float2 bb = *(const float2*)(bias + c);
                    v0 += bb.x; v1 += bb.y;
                }
                if (ACT == 1) { v0 = gelu_f(v0); v1 = gelu_f(v1); }
                const size_t off = (size_t)row * ldC + c;
                if (res) {
                    float2 r = *(const float2*)(res + off);
                    v0 += r.x; v1 += r.y;
                }
                if (dupD) {
                    *(float2*)(dupD + off) = *(const float2*)(dupS + off);
                }
                if (C) {
                    float2 o; o.x = v0; o.y = v1;
                    *(float2*)(C + off) = o;
                }
                if (C16) {
                    __half2 o16 = __floats2half2_rn(v0, v1);
                    *(__half2*)(C16 + off) = o16;
                }
            }
        }
    }
}

// ---------------------------------------------------------------------------
// FUSED edge GEMM + scatter (fp16 mma core). K = EEMB = 128.
// m = gelu(acc + P[src] + Q[dst]); red.global.add.v4 into C[dst].
// ---------------------------------------------------------------------------
__global__ void __launch_bounds__(256, 4) mma_edge_k(
    int wOff, const int* __restrict__ ei, int Cid)
{
    __shared__ __half As[2][64][24];
    __shared__ __half Bs[2][128][24];
    __shared__ int sSrc[64], sDst[64];

    const __half* __restrict__ A = g_e16;
    const __half* __restrict__ W = g_wt16 + wOff;
    float* __restrict__ C = bufsel(Cid);

    const int tid  = threadIdx.x;
    const int bm   = blockIdx.x * 64;
    const int bn   = blockIdx.y * 128;
    const int w    = tid >> 5;
    const int lane = tid & 31;
    const int g    = lane >> 2;
    const int tq   = lane & 3;
    const int wm   = (w & 1) * 32;
    const int wn   = (w >> 1) * 32;

    if (tid < 64) {
        sSrc[tid] = ei[bm + tid];
        sDst[tid] = ei[NE + bm + tid];
    }

    const int lrow = tid >> 1;
    const int lhf  = tid & 1;
    const __half* Ag = A + (size_t)(bm + (lrow & 63)) * EEMB + lhf * 8;
    const __half* Bg = W + (size_t)(bn + lrow) * EEMB + lhf * 8;

    unsigned dA[2], dB[2];
#pragma unroll
    for (int s = 0; s < 2; s++) {
        dA[s] = (unsigned)__cvta_generic_to_shared(&As[s][lrow & 63][lhf * 8]);
        dB[s] = (unsigned)__cvta_generic_to_shared(&Bs[s][lrow][lhf * 8]);
    }
    const bool doA = (tid < 128);

    float acc[2][4][4];
#pragma unroll
    for (int mi = 0; mi < 2; mi++)
#pragma unroll
        for (int ni = 0; ni < 4; ni++)
#pragma unroll
            for (int r = 0; r < 4; r++) acc[mi][ni][r] = 0.f;

    if (doA) cp16(dA[0], Ag);
    cp16(dB[0], Bg);
    asm volatile("cp.async.commit_group;" ::: "memory");

    const int niter = EEMB / 16;   // 8
    for (int it = 0; it < niter; it++) {
        const int cur = it & 1;
        if (it + 1 < niter) {
            const int nxt = (it + 1) & 1;
            const int k0  = (it + 1) * 16;
            if (doA) cp16(dA[nxt], Ag + k0);
            cp16(dB[nxt], Bg + k0);
            asm volatile("cp.async.commit_group;" ::: "memory");
            asm volatile("cp.async.wait_group 1;" ::: "memory");
        } else {
            asm volatile("cp.async.wait_group 0;" ::: "memory");
        }
        __syncthreads();

        unsigned a[2][4], b[4][2];
#pragma unroll
        for (int mi = 0; mi < 2; mi++) {
            const int m0 = wm + mi * 16 + g;
            a[mi][0] = *(const unsigned*)&As[cur][m0][2 * tq];
            a[mi][1] = *(const unsigned*)&As[cur][m0 + 8][2 * tq];
            a[mi][2] = *(const unsigned*)&As[cur][m0][2 * tq + 8];
            a[mi][3] = *(const unsigned*)&As[cur][m0 + 8][2 * tq + 8];
        }
#pragma unroll
        for (int ni = 0; ni < 4; ni++) {
            const int n0 = wn + ni * 8 + g;
            b[ni][0] = *(const unsigned*)&Bs[cur][n0][2 * tq];
            b[ni][1] = *(const unsigned*)&Bs[cur][n0][2 * tq + 8];
        }
#pragma unroll
        for (int mi = 0; mi < 2; mi++)
#pragma unroll
            for (int ni = 0; ni < 4; ni++)
                mma_f16(acc[mi][ni], a[mi], b[ni]);
        __syncthreads();   // also orders sSrc/sDst before epilogue reads
    }

    // fused scatter epilogue (v4 reductions via lane^1 butterfly)
    const bool odd = (tq & 1);
#pragma unroll
    for (int mi = 0; mi < 2; mi++) {
#pragma unroll
        for (int h = 0; h < 2; h++) {
            const int lr = wm + mi * 16 + g + h * 8;
            const int s = sSrc[lr];
            const int d = sDst[lr];
            const float* Pp = g_P + (size_t)s * DIM;
            const float* Qp = g_Q + (size_t)d * DIM;
            float* Op = C + (size_t)d * DIM;
#pragma unroll
            for (int p = 0; p < 2; p++) {
                float s0 = odd ? acc[mi][2*p][h*2+0] : acc[mi][2*p+1][h*2+0];
                float s1 = odd ? acc[mi][2*p][h*2+1] : acc[mi][2*p+1][h*2+1];
                float r0 = __shfl_xor_sync(0xffffffffu, s0, 1);
                float r1 = __shfl_xor_sync(0xffffffffu, s1, 1);
                float o0 = odd ? acc[mi][2*p+1][h*2+0] : acc[mi][2*p][h*2+0];
                float o1 = odd ? acc[mi][2*p+1][h*2+1] : acc[mi][2*p][h*2+1];
                float4 v;
                if (odd) { v.x = r0; v.y = r1; v.z = o0; v.w = o1; }
                else     { v.x = o0; v.y = o1; v.z = r0; v.w = r1; }

                const int c = bn + wn + p * 16 + (tq & 1) * 8 + (tq >> 1) * 4;
                float4 pv = *(const float4*)(Pp + c);
                float4 qv = *(const float4*)(Qp + c);
                v.x = gelu_f(v.x + pv.x + qv.x);
                v.y = gelu_f(v.y + pv.y + qv.y);
                v.z = gelu_f(v.z + pv.z + qv.z);
                v.w = gelu_f(v.w + pv.w + qv.w);

                asm volatile("red.global.add.v4.f32 [%0], {%1, %2, %3, %4};"
                             :: "l"(Op + c), "f"(v.x), "f"(v.y), "f"(v.z), "f"(v.w)
                             : "memory");
            }
        }
    }
}

// ---------------------------------------------------------------------------
extern "C" void kernel_launch(void* const* d_in, const int* in_sizes, int n_in,
                              void* d_out, int out_size)
{
    const float* x     = (const float*)d_in[0];
    const int*   ei    = (const int*)d_in[1];
    const float* attr  = (const float*)d_in[2];
    const float* ee_w1 = (const float*)d_in[3];
    const float* ee_b1 = (const float*)d_in[4];
    const float* ee_w2 = (const float*)d_in[5];
    const float* ee_b2 = (const float*)d_in[6];
    const float* ff1_w = (const float*)d_in[7];
    const float* ff1_b = (const float*)d_in[8];
    const float* mp1_w = (const float*)d_in[9];
    const float* mp1_b = (const float*)d_in[10];
    const float* mp2_w = (const float*)d_in[11];
    const float* mp2_b = (const float*)d_in[12];
    const float* ff2_w = (const float*)d_in[13];
    const float* ff2_b = (const float*)d_in[14];
    float* out = (float*)d_out;

    const int n4 = NN * DIM / 4;
    const int cb = (n4 + 255) / 256;
    const dim3 gN(NN / 64, 2);       // node GEMMs (N=256)
    const dim3 gE(NE / 64, 2);       // fused edge GEMM+scatter (N=256)
    const dim3 gEE(NE / 64, 1);      // edge-embed layer-2 GEMM (N=128)

    // transpose + fp16-convert all weights into g_wt16 ([N][K])
    for (int i = 0; i < DEPTH; i++) {
        const float* m1 = mp1_w + (size_t)i * 640 * DIM;
        const float* m2 = mp2_w + (size_t)i * 640 * DIM;
        cvtwt16_k<<<(65536 + 255) / 256, 256>>>(ff1_w + (size_t)i * 65536, WT_FF1(i), 256, 256);
        cvtwt16_k<<<(65536 + 255) / 256, 256>>>(m1,                        WT_A1(i),  256, 256);
        cvtwt16_k<<<(65536 + 255) / 256, 256>>>(m1 + 256 * DIM,            WT_B1(i),  256, 256);
        cvtwt16_k<<<(32768 + 255) / 256, 256>>>(m1 + 512 * DIM,            WT_C1(i),  128, 256);
        cvtwt16_k<<<(65536 + 255) / 256, 256>>>(m2,                        WT_A2(i),  256, 256);
        cvtwt16_k<<<(65536 + 255) / 256, 256>>>(m2 + 256 * DIM,            WT_B2(i),  256, 256);
        cvtwt16_k<<<(32768 + 255) / 256, 256>>>(m2 + 512 * DIM,            WT_C2(i),  128, 256);
        cvtwt16_k<<<(65536 + 255) / 256, 256>>>(ff2_w + (size_t)i * 65536, WT_FF2(i), 256, 256);
    }
    cvtwt16_k<<<(16384 + 255) / 256, 256>>>(ee_w2, WT_EE2, 128, 128);

    copy_in_k<<<cb, 256>>>(x, n4);

    // edge embedder: layer1 SIMT -> hid16; layer2 fp16 GEMM -> e16
    ee1_k<<<NE / 2, 256>>>(attr, ee_w1, ee_b1);
    mma_gemm_k<0><<<gEE, 256>>>(H_HID, WT_EE2, ee_b2, -1, -1, -1,
                                -1, nullptr, H_E16, EEMB, EEMB);

    for (int i = 0; i < DEPTH; i++) {
        // hA = gelu(x @ ff1 + b); write fp32 hA + fp16 h16
        cvt16_k<<<cb, 256>>>(B_X, n4);
        mma_gemm_k<1><<<gN, 256>>>(H_A16, WT_FF1(i), ff1_b + i * DIM, -1, -1, -1,
                                   B_HA, nullptr, H_H16, DIM, DIM);

        // message pass 1 (A = h16): P, Q (+dup hA->hB), fused edge scatter
        mma_gemm_k<0><<<gN, 256>>>(H_H16, WT_A1(i), mp1_b + i * DIM, -1, -1, -1,
                                   B_P, nullptr, -1, DIM, DIM);
        mma_gemm_k<0><<<gN, 256>>>(H_H16, WT_B1(i), nullptr, -1, B_HA, B_HB,
                                   B_Q, nullptr, -1, DIM, DIM);
        mma_edge_k<<<gE, 256>>>(WT_C1(i), ei, B_HB);

        // message pass 2 (hB dirty): cvt -> a16; P, Q (+dup hB->hA), edge
        cvt16_k<<<cb, 256>>>(B_HB, n4);
        mma_gemm_k<0><<<gN, 256>>>(H_A16, WT_A2(i), mp2_b + i * DIM, -1, -1, -1,
                                   B_P, nullptr, -1, DIM, DIM);
        mma_gemm_k<0><<<gN, 256>>>(H_A16, WT_B2(i), nullptr, -1, B_HB, B_HA,
                                   B_Q, nullptr, -1, DIM, DIM);
        mma_edge_k<<<gE, 256>>>(WT_C2(i), ei, B_HA);

        // x = x + hA @ ff2 + b (hA dirty): cvt -> a16; last layer -> d_out
        cvt16_k<<<cb, 256>>>(B_HA, n4);
        mma_gemm_k<0><<<gN, 256>>>(H_A16, WT_FF2(i), ff2_b + i * DIM, B_X, -1, -1,
                                   B_X, (i == DEPTH - 1) ? out : nullptr, -1,
                                   DIM, DIM);
    }
}